// round 6
// baseline (speedup 1.0000x reference)
#include <cuda_runtime.h>
#include <math.h>

#define SZ 160
#define NB 8
#define NC 64
#define HW 256
#define CCHUNKS 32
#define CPER 2          // NC / CCHUNKS
#define KTILE 16

typedef unsigned long long u64;

// ---- packed f32x2 helpers (Blackwell FFMA2: only reachable via PTX) ----
__device__ __forceinline__ void fma2(u64& d, u64 a, u64 b) {
    asm("fma.rn.f32x2 %0, %1, %2, %0;" : "+l"(d) : "l"(a), "l"(b));
}
__device__ __forceinline__ u64 dup2(float v) {
    u64 r; asm("mov.b64 %0, {%1, %1};" : "=l"(r) : "f"(v)); return r;
}
__device__ __forceinline__ float2 unpk(u64 v) {
    float2 f; asm("mov.b64 {%0, %1}, %2;" : "=f"(f.x), "=f"(f.y) : "l"(v)); return f;
}

// -------- scratch (no allocations allowed; __device__ globals) --------
__device__ float g_x160[NB * NC * SZ * SZ];                 // 52.4 MB
__device__ float g_part[2 * CCHUNKS * NB * NC * SZ];        // 21 MB split-K partials
__device__ float g_bvec[NB * NC * SZ];
__device__ float g_cvec[NB * NC * SZ];
__device__ float g_s[NB * NC];

// ---------------- Kernel 1: nearest downsample 256->160 ----------------
__global__ void k_down(const float* __restrict__ x) {
    int bc = blockIdx.x;  // 0..511 = batch*NC + ch
    const float* __restrict__ src = x + (size_t)bc * HW * HW;
    float* __restrict__ dst = g_x160 + (size_t)bc * SZ * SZ;
    for (int e = threadIdx.x; e < SZ * SZ; e += blockDim.x) {
        int h = e / SZ;
        int w = e - h * SZ;
        int hi = (h * 8) / 5;
        int wi = (w * 8) / 5;
        dst[e] = __ldg(&src[hi * HW + wi]);
    }
}

// ---------------- Kernel 2: split-K GEMMs (packed f32x2 math) ----------------
// which==0: b_pre[b,o,h] = sum_{c,w} x160[b,c,h,w] * Wb[o,c,w]   (m=h, k=w)
// which==1: c_pre[b,o,w] = sum_{c,h} x160[b,c,h,w] * Wc[o,c,h]   (m=w, k=h)
// 160 threads, tile M=160 x N=64, per-thread 8(m) x 8(n) as 4 m-pairs x 8 n.
// Thread t: ty=t>>3 owns m=ty*8..+7; tx=t&7 owns n = tx + 8*k (k=0..7).
// B stored duplicated in smem so the dup operand is a direct LDS.64.
__global__ __launch_bounds__(160, 3)
void k_gemm(const float* __restrict__ WbP, const float* __restrict__ WcP) {
    __shared__ __align__(16) float As[KTILE * 164];   // [kk][m], pad 164
    __shared__ __align__(16) float BsD[KTILE * 132];  // [kk][2*o {dup}], pad 132

    const int cc    = blockIdx.x;   // 0..CCHUNKS-1
    const int batch = blockIdx.y;   // 0..7
    const int which = blockIdx.z;   // 0 or 1
    const float* __restrict__ W = which ? WcP : WbP;

    const int t  = threadIdx.x;     // 0..159
    const int ty = t >> 3;          // 0..19 -> m block of 8
    const int tx = t & 7;           // 0..7  -> n = tx + 8k

    u64 acc2[4][8];
#pragma unroll
    for (int i = 0; i < 4; i++)
#pragma unroll
        for (int j = 0; j < 8; j++) acc2[i][j] = 0ull;  // (0.f, 0.f)

    for (int cl = 0; cl < CPER; cl++) {
        const int c = cc * CPER + cl;
        const float* __restrict__ xb = g_x160 + (size_t)(batch * NC + c) * SZ * SZ;
        const float* __restrict__ wb = W + (size_t)c * SZ;  // W[o*NC*SZ + c*SZ + k]

        for (int k0 = 0; k0 < SZ; k0 += KTILE) {
            // ---- A tile ----
            if (which == 0) {
#pragma unroll
                for (int i = 0; i < 16; i++) {
                    int e  = i * 160 + t;
                    int m  = e >> 4;
                    int kk = e & 15;
                    As[kk * 164 + m] = xb[m * SZ + k0 + kk];
                }
            } else {
#pragma unroll
                for (int i = 0; i < 16; i++) {
                    As[i * 164 + t] = xb[(k0 + i) * SZ + t];
                }
            }
            // ---- B tile, duplicated pairs ----
            for (int e = t; e < KTILE * NC; e += 160) {
                int o  = e >> 4;
                int kk = e & 15;
                float w = wb[(size_t)o * (NC * SZ) + k0 + kk];
                *(u64*)&BsD[kk * 132 + 2 * o] = dup2(w);
            }
            __syncthreads();

#pragma unroll 4
            for (int kk = 0; kk < KTILE; kk++) {
                const ulonglong2* ap =
                    (const ulonglong2*)&As[kk * 164 + ty * 8];
                ulonglong2 av0 = ap[0];
                ulonglong2 av1 = ap[1];
                u64 am[4] = {av0.x, av0.y, av1.x, av1.y};
                u64 bd[8];
#pragma unroll
                for (int k = 0; k < 8; k++)
                    bd[k] = *(const u64*)&BsD[kk * 132 + 2 * (tx + 8 * k)];
#pragma unroll
                for (int k = 0; k < 8; k++)
#pragma unroll
                    for (int mp = 0; mp < 4; mp++)
                        fma2(acc2[mp][k], am[mp], bd[k]);
            }
            __syncthreads();
        }
    }

    // ---- write partials: pout[o*SZ + m], o = tx + 8*ni, m = ty*8 + 0..7 ----
    float* __restrict__ pout =
        g_part + ((size_t)(which * CCHUNKS + cc) * NB + batch) * (NC * SZ);
#pragma unroll
    for (int ni = 0; ni < 8; ni++) {
        int o = tx + 8 * ni;
        float2 f0 = unpk(acc2[0][ni]);
        float2 f1 = unpk(acc2[1][ni]);
        float2 f2 = unpk(acc2[2][ni]);
        float2 f3 = unpk(acc2[3][ni]);
        *(float4*)&pout[o * SZ + ty * 8]     = make_float4(f0.x, f0.y, f1.x, f1.y);
        *(float4*)&pout[o * SZ + ty * 8 + 4] = make_float4(f2.x, f2.y, f3.x, f3.y);
    }
}

// ---------------- Kernel 3: reduce partials, BN-fold, SiLU, s = <b,c> ----------------
__global__ void k_finish(const float* __restrict__ gb, const float* __restrict__ bb,
                         const float* __restrict__ gc, const float* __restrict__ bc) {
    const int o     = blockIdx.x;   // channel
    const int batch = blockIdx.y;
    const int t     = threadIdx.x;  // 0..159

    float bsum = 0.f, csum = 0.f;
    const size_t inner = (size_t)o * SZ + t;
    for (int cc = 0; cc < CCHUNKS; cc++) {
        bsum += g_part[((size_t)(cc) * NB + batch) * (NC * SZ) + inner];
        csum += g_part[((size_t)(CCHUNKS + cc) * NB + batch) * (NC * SZ) + inner];
    }
    float bp = bsum * gb[o] + bb[o];
    float bv = bp / (1.f + expf(-bp));
    float cp = csum * gc[o] + bc[o];
    float cv = cp / (1.f + expf(-cp));

    const size_t idx = (size_t)(batch * NC + o) * SZ + t;
    g_bvec[idx] = bv;
    g_cvec[idx] = cv;

    __shared__ float red[SZ];
    red[t] = bv * cv;
    __syncthreads();
    if (t == 0) {
        float s = 0.f;
        for (int i = 0; i < SZ; i++) s += red[i];
        g_s[batch * NC + o] = s;
    }
}

// ---------------- Kernel 4: rank-1 update + upsample, 4-way Y-split ----------------
// grid (512, 4): block q owns Y in [64q, 64q+64) -> h in [40q, 40q+40) exactly.
__global__ __launch_bounds__(256, 6)
void k_final(float* __restrict__ out) {
    __shared__ float bv[SZ];
    __shared__ float cvE[HW];   // cv[wi(X)] pre-expanded
    __shared__ float ps[40];    // this quarter's (x160[h,:]·b)*s

    const int bc = blockIdx.x;      // batch*NC + ch
    const int q  = blockIdx.y;      // Y quarter
    const int t  = threadIdx.x;     // 0..255
    const float* __restrict__ xsrc = g_x160 + (size_t)bc * SZ * SZ;

    if (t < SZ) bv[t] = g_bvec[(size_t)bc * SZ + t];
    cvE[t] = g_cvec[(size_t)bc * SZ + ((t * 5) >> 3)];
    __syncthreads();

    const float sval = g_s[bc];
    const int warp = t >> 5, lane = t & 31;
    for (int hh = warp; hh < 40; hh += 8) {
        const int h = 40 * q + hh;
        float p = 0.f;
#pragma unroll
        for (int k = 0; k < 5; k++) {
            int w = lane + 32 * k;
            p += xsrc[h * SZ + w] * bv[w];
        }
#pragma unroll
        for (int off = 16; off; off >>= 1) p += __shfl_down_sync(0xffffffffu, p, off);
        if (lane == 0) ps[hh] = p * sval;
    }
    __syncthreads();

    const int r  = t >> 6;          // 0..3 (row in 4-row group)
    const int xq = t & 63;          // float4 column
    const int X0 = xq * 4;
    const int wi0 = (X0 * 5) >> 3;
    const int wi1 = ((X0 + 1) * 5) >> 3;
    const int wi2 = ((X0 + 2) * 5) >> 3;
    const int wi3 = ((X0 + 3) * 5) >> 3;
    const float c0 = cvE[X0], c1 = cvE[X0 + 1], c2 = cvE[X0 + 2], c3 = cvE[X0 + 3];

    float* __restrict__ obase = out + (size_t)bc * HW * HW;
    const int Ybeg = 64 * q;
#pragma unroll 2
    for (int Y0 = Ybeg; Y0 < Ybeg + 64; Y0 += 4) {
        const int Y = Y0 + r;
        const int h = (Y * 5) >> 3;
        const float* __restrict__ xr = xsrc + h * SZ;
        const float pv = ps[h - 40 * q];
        float4 v;
        v.x = xr[wi0] + pv * c0;
        v.y = xr[wi1] + pv * c1;
        v.z = xr[wi2] + pv * c2;
        v.w = xr[wi3] + pv * c3;
        *(float4*)&obase[Y * HW + X0] = v;
    }
}

// ---------------- launch ----------------
extern "C" void kernel_launch(void* const* d_in, const int* in_sizes, int n_in,
                              void* d_out, int out_size) {
    const float* x  = (const float*)d_in[0];
    const float* Wb = (const float*)d_in[1];
    const float* Wc = (const float*)d_in[2];
    const float* gb = (const float*)d_in[3];
    const float* bb = (const float*)d_in[4];
    const float* gc = (const float*)d_in[5];
    const float* bc = (const float*)d_in[6];
    float* out = (float*)d_out;

    k_down<<<NB * NC, 256>>>(x);
    k_gemm<<<dim3(CCHUNKS, NB, 2), 160>>>(Wb, Wc);
    k_finish<<<dim3(NC, NB), 160>>>(gb, bb, gc, bc);
    k_final<<<dim3(NB * NC, 4), 256>>>(out);
}

// round 7
// speedup vs baseline: 1.2087x; 1.2087x over previous
#include <cuda_runtime.h>
#include <math.h>

#define SZ 160
#define NB 8
#define NC 64
#define HW 256
#define CCHUNKS 32
#define CPER 2          // NC / CCHUNKS
#define KTILE 16

// -------- scratch (no allocations allowed; __device__ globals) --------
__device__ float g_x160[NB * NC * SZ * SZ];                 // 52.4 MB
__device__ float g_part[2 * CCHUNKS * NB * NC * SZ];        // 21 MB split-K partials
__device__ float g_bvec[NB * NC * SZ];
__device__ float g_cvec[NB * NC * SZ];
__device__ float g_s[NB * NC];

// ---------------- Kernel 1: nearest downsample 256->160 ----------------
__global__ void k_down(const float* __restrict__ x) {
    int bc = blockIdx.x;  // 0..511 = batch*NC + ch
    const float* __restrict__ src = x + (size_t)bc * HW * HW;
    float* __restrict__ dst = g_x160 + (size_t)bc * SZ * SZ;
    for (int e = threadIdx.x; e < SZ * SZ; e += blockDim.x) {
        int h = e / SZ;
        int w = e - h * SZ;
        int hi = (h * 8) / 5;
        int wi = (w * 8) / 5;
        dst[e] = __ldg(&src[hi * HW + wi]);
    }
}

// ---------------- Kernel 2: split-K GEMMs (exact R5 scalar, measured-good) ----------------
// which==0: b_pre[b,o,h] = sum_{c,w} x160[b,c,h,w] * Wb[o,c,w]   (m=h, k=w)
// which==1: c_pre[b,o,w] = sum_{c,h} x160[b,c,h,w] * Wc[o,c,h]   (m=w, k=h)
__global__ __launch_bounds__(160, 4)
void k_gemm(const float* __restrict__ WbP, const float* __restrict__ WcP) {
    __shared__ __align__(16) float As[KTILE * 164];  // [kk][m], padded row 164
    __shared__ __align__(16) float Bs[KTILE * 68];   // [kk][o], padded row 68

    const int cc    = blockIdx.x;   // 0..CCHUNKS-1
    const int batch = blockIdx.y;   // 0..7
    const int which = blockIdx.z;   // 0 or 1
    const float* __restrict__ W = which ? WcP : WbP;

    const int t  = threadIdx.x;     // 0..159
    const int ty = t >> 3;          // 0..19 -> m block of 8
    const int tx = t & 7;           // 0..7  -> n block of 8

    float acc[8][8];
#pragma unroll
    for (int i = 0; i < 8; i++)
#pragma unroll
        for (int j = 0; j < 8; j++) acc[i][j] = 0.f;

    for (int cl = 0; cl < CPER; cl++) {
        const int c = cc * CPER + cl;
        const float* __restrict__ xb = g_x160 + (size_t)(batch * NC + c) * SZ * SZ;
        const float* __restrict__ wb = W + (size_t)c * SZ;  // W[o*NC*SZ + c*SZ + k]

        for (int k0 = 0; k0 < SZ; k0 += KTILE) {
            if (which == 0) {
#pragma unroll
                for (int i = 0; i < 16; i++) {
                    int e  = i * 160 + t;
                    int m  = e >> 4;
                    int kk = e & 15;
                    As[kk * 164 + m] = xb[m * SZ + k0 + kk];
                }
            } else {
#pragma unroll
                for (int i = 0; i < 16; i++) {
                    As[i * 164 + t] = xb[(k0 + i) * SZ + t];
                }
            }
            for (int e = t; e < KTILE * NC; e += 160) {
                int o  = e >> 4;
                int kk = e & 15;
                Bs[kk * 68 + o] = wb[(size_t)o * (NC * SZ) + k0 + kk];
            }
            __syncthreads();

#pragma unroll 4
            for (int kk = 0; kk < KTILE; kk++) {
                float4 a0 = *(const float4*)&As[kk * 164 + ty * 8];
                float4 a1 = *(const float4*)&As[kk * 164 + ty * 8 + 4];
                float4 b0 = *(const float4*)&Bs[kk * 68 + tx * 8];
                float4 b1 = *(const float4*)&Bs[kk * 68 + tx * 8 + 4];
                float am[8] = {a0.x, a0.y, a0.z, a0.w, a1.x, a1.y, a1.z, a1.w};
                float bn[8] = {b0.x, b0.y, b0.z, b0.w, b1.x, b1.y, b1.z, b1.w};
#pragma unroll
                for (int mi = 0; mi < 8; mi++)
#pragma unroll
                    for (int ni = 0; ni < 8; ni++)
                        acc[mi][ni] = fmaf(am[mi], bn[ni], acc[mi][ni]);
            }
            __syncthreads();
        }
    }

    float* __restrict__ pout =
        g_part + ((size_t)(which * CCHUNKS + cc) * NB + batch) * (NC * SZ);
#pragma unroll
    for (int ni = 0; ni < 8; ni++) {
        int o = tx * 8 + ni;
#pragma unroll
        for (int mi = 0; mi < 8; mi += 4) {
            float4 v = make_float4(acc[mi][ni], acc[mi + 1][ni],
                                   acc[mi + 2][ni], acc[mi + 3][ni]);
            *(float4*)&pout[o * SZ + ty * 8 + mi] = v;
        }
    }
}

// ---------------- Kernel 3: reduce partials, BN-fold, SiLU, s = <b,c> ----------------
__global__ void k_finish(const float* __restrict__ gb, const float* __restrict__ bb,
                         const float* __restrict__ gc, const float* __restrict__ bc) {
    const int o     = blockIdx.x;   // channel
    const int batch = blockIdx.y;
    const int t     = threadIdx.x;  // 0..159

    float bsum = 0.f, csum = 0.f;
    const size_t inner = (size_t)o * SZ + t;
    for (int cc = 0; cc < CCHUNKS; cc++) {
        bsum += g_part[((size_t)(cc) * NB + batch) * (NC * SZ) + inner];
        csum += g_part[((size_t)(CCHUNKS + cc) * NB + batch) * (NC * SZ) + inner];
    }
    float bp = bsum * gb[o] + bb[o];
    float bv = bp / (1.f + expf(-bp));
    float cp = csum * gc[o] + bc[o];
    float cv = cp / (1.f + expf(-cp));

    const size_t idx = (size_t)(batch * NC + o) * SZ + t;
    g_bvec[idx] = bv;
    g_cvec[idx] = cv;

    __shared__ float red[SZ];
    red[t] = bv * cv;
    __syncthreads();
    if (t == 0) {
        float s = 0.f;
        for (int i = 0; i < SZ; i++) s += red[i];
        g_s[batch * NC + o] = s;
    }
}

// ---------------- Kernel 4: rank-1 update + upsample, 4-way Y-split ----------------
// grid (512, 4): block q owns Y in [64q, 64q+64) -> h in [40q, 40q+40) exactly.
// (exact R6 version, measured 38.7us)
__global__ __launch_bounds__(256, 6)
void k_final(float* __restrict__ out) {
    __shared__ float bv[SZ];
    __shared__ float cvE[HW];   // cv[wi(X)] pre-expanded
    __shared__ float ps[40];    // this quarter's (x160[h,:]·b)*s

    const int bc = blockIdx.x;      // batch*NC + ch
    const int q  = blockIdx.y;      // Y quarter
    const int t  = threadIdx.x;     // 0..255
    const float* __restrict__ xsrc = g_x160 + (size_t)bc * SZ * SZ;

    if (t < SZ) bv[t] = g_bvec[(size_t)bc * SZ + t];
    cvE[t] = g_cvec[(size_t)bc * SZ + ((t * 5) >> 3)];
    __syncthreads();

    const float sval = g_s[bc];
    const int warp = t >> 5, lane = t & 31;
    for (int hh = warp; hh < 40; hh += 8) {
        const int h = 40 * q + hh;
        float p = 0.f;
#pragma unroll
        for (int k = 0; k < 5; k++) {
            int w = lane + 32 * k;
            p += xsrc[h * SZ + w] * bv[w];
        }
#pragma unroll
        for (int off = 16; off; off >>= 1) p += __shfl_down_sync(0xffffffffu, p, off);
        if (lane == 0) ps[hh] = p * sval;
    }
    __syncthreads();

    const int r  = t >> 6;          // 0..3 (row in 4-row group)
    const int xq = t & 63;          // float4 column
    const int X0 = xq * 4;
    const int wi0 = (X0 * 5) >> 3;
    const int wi1 = ((X0 + 1) * 5) >> 3;
    const int wi2 = ((X0 + 2) * 5) >> 3;
    const int wi3 = ((X0 + 3) * 5) >> 3;
    const float c0 = cvE[X0], c1 = cvE[X0 + 1], c2 = cvE[X0 + 2], c3 = cvE[X0 + 3];

    float* __restrict__ obase = out + (size_t)bc * HW * HW;
    const int Ybeg = 64 * q;
#pragma unroll 2
    for (int Y0 = Ybeg; Y0 < Ybeg + 64; Y0 += 4) {
        const int Y = Y0 + r;
        const int h = (Y * 5) >> 3;
        const float* __restrict__ xr = xsrc + h * SZ;
        const float pv = ps[h - 40 * q];
        float4 v;
        v.x = xr[wi0] + pv * c0;
        v.y = xr[wi1] + pv * c1;
        v.z = xr[wi2] + pv * c2;
        v.w = xr[wi3] + pv * c3;
        *(float4*)&obase[Y * HW + X0] = v;
    }
}

// ---------------- launch ----------------
extern "C" void kernel_launch(void* const* d_in, const int* in_sizes, int n_in,
                              void* d_out, int out_size) {
    const float* x  = (const float*)d_in[0];
    const float* Wb = (const float*)d_in[1];
    const float* Wc = (const float*)d_in[2];
    const float* gb = (const float*)d_in[3];
    const float* bb = (const float*)d_in[4];
    const float* gc = (const float*)d_in[5];
    const float* bc = (const float*)d_in[6];
    float* out = (float*)d_out;

    k_down<<<NB * NC, 256>>>(x);
    k_gemm<<<dim3(CCHUNKS, NB, 2), 160>>>(Wb, Wc);
    k_finish<<<dim3(NC, NB), 160>>>(gb, bb, gc, bc);
    k_final<<<dim3(NB * NC, 4), 256>>>(out);
}

// round 10
// speedup vs baseline: 1.3350x; 1.1045x over previous
#include <cuda_runtime.h>
#include <cuda_bf16.h>
#include <math.h>
#include <stdint.h>

#define SZ 160
#define NB 8
#define NC 64
#define HW 256
#define NCH 16          // split-K channel chunks (4 channels per block)
#define CPB (NC / NCH)  // 4 channels per block

// -------- scratch (no allocations allowed; __device__ globals) --------
__device__ float g_x160[NB * NC * SZ * SZ];            // 52.4 MB
__device__ float g_part[2 * NCH * NB * NC * SZ];       // fp32 split-K partials
__device__ float g_bvec[NB * NC * SZ];
__device__ float g_cvec[NB * NC * SZ];
__device__ float g_s[NB * NC];

// ---------------- Kernel 1: nearest downsample 256->160 ----------------
__global__ void k_down(const float* __restrict__ x) {
    int bc = blockIdx.x;
    const float* __restrict__ src = x + (size_t)bc * HW * HW;
    float* __restrict__ dst = g_x160 + (size_t)bc * SZ * SZ;
    for (int e = threadIdx.x; e < SZ * SZ; e += blockDim.x) {
        int h = e / SZ;
        int w = e - h * SZ;
        dst[e] = __ldg(&src[((h * 8) / 5) * HW + (w * 8) / 5]);
    }
}

// ---------------- Kernel 2: warp-level HMMA bf16-split GEMM ----------------
// D[m,o] = sum_{c,k} x[m,(c,k)] * W[o,(c,k)];  x = hi+lo, W = hi+lo in bf16;
// compute hi*hi + hi*lo + lo*hi in fp32 accum (lo*lo dropped, ~2^-18 rel).
// mma.sync.m16n8k16.row.col documented fragment mapping (lane L, q=L&3, r=L>>2):
//   A reg j: (row = r + (j&1)*8, k = 2q + (j>>1)*8 {pair k,k+1})
//   B reg j: (k = 2q + j*8 {pair},  col = r)
//   C reg j: (row = r + (j>>1)*8, col = 2q + (j&1))
// Fragments staged pre-packed in smem: A lane-major 16B -> LDS.128; B 8B -> LDS.64.

__device__ __forceinline__ uint32_t pack_hi(float a, float b) {
    __nv_bfloat162 h = __floats2bfloat162_rn(a, b);   // (lo half = a, hi half = b)
    return *(uint32_t*)&h;
}
__device__ __forceinline__ uint32_t pack_lo(float a, float b) {
    __nv_bfloat16 ha = __float2bfloat16(a), hb = __float2bfloat16(b);
    __nv_bfloat16 la = __float2bfloat16(a - __bfloat162float(ha));
    __nv_bfloat16 lb = __float2bfloat16(b - __bfloat162float(hb));
    return ((uint32_t)__bfloat16_as_ushort(lb) << 16) | __bfloat16_as_ushort(la);
}

__device__ __forceinline__ void hmma(float* c, const uint32_t* a, const uint32_t* b) {
    asm volatile(
        "mma.sync.aligned.m16n8k16.row.col.f32.bf16.bf16.f32 "
        "{%0,%1,%2,%3}, {%4,%5,%6,%7}, {%8,%9}, {%0,%1,%2,%3};"
        : "+f"(c[0]), "+f"(c[1]), "+f"(c[2]), "+f"(c[3])
        : "r"(a[0]), "r"(a[1]), "r"(a[2]), "r"(a[3]), "r"(b[0]), "r"(b[1]));
}

// A frag smem: [mt(10)][ks(2)][mat(2)][lane(32)][reg(4)] b32 = 20 KB
// B frag smem: [ks(2)][mat(2)][nt(8)][lane(32)][reg(2)]  b32 = 8 KB
#define A_OFF(mt, ks, mat, lane) ((((((mt)*2 + (ks))*2 + (mat))*32 + (lane))*4))
#define B_OFF(ks, mat, nt, lane) ((((((ks)*2 + (mat))*8 + (nt))*32 + (lane))*2))

__global__ __launch_bounds__(256, 2)
void k_mma(const float* __restrict__ WbP, const float* __restrict__ WcP) {
    __shared__ __align__(16) uint32_t Af[10 * 2 * 2 * 32 * 4];  // 20480 B
    __shared__ __align__(16) uint32_t Bf[2 * 2 * 8 * 32 * 2];   //  8192 B

    const int cc    = blockIdx.x;   // 0..NCH-1
    const int batch = blockIdx.y;   // 0..7
    const int which = blockIdx.z;   // 0 or 1
    const float* __restrict__ W = which ? WcP : WbP;

    const int t    = threadIdx.x;
    const int wid  = t >> 5;
    const int lane = t & 31;
    const int mgrp = wid >> 2;      // 0..1 -> m rows [80*mgrp, 80*mgrp+80)
    const int ngrp = wid & 3;       // 0..3 -> n tiles ngrp*2, ngrp*2+1

    float acc[5][2][4];
#pragma unroll
    for (int i = 0; i < 5; i++)
#pragma unroll
        for (int j = 0; j < 2; j++)
#pragma unroll
            for (int r = 0; r < 4; r++) acc[i][j][r] = 0.f;

    for (int slice = 0; slice < CPB * 5; slice++) {
        const int c  = cc * CPB + slice / 5;
        const int k0 = (slice % 5) * 32;
        const float* __restrict__ xb = g_x160 + (size_t)(batch * NC + c) * SZ * SZ;
        const float* __restrict__ wb = W + (size_t)c * SZ;  // + o*NC*SZ + k

        // ---- stage A fragments (hi: mat 0, lo: mat 1) ----
        // e -> (mt, ks, lane, reg); 10*2*32*4 = 2560 elems, 10 iters
        for (int e = t; e < 2560; e += 256) {
            int reg = e & 3, ln = (e >> 2) & 31, ks = (e >> 7) & 1, mt = e >> 8;
            int m = mt * 16 + (ln >> 2) + (reg & 1) * 8;
            int k = k0 + ks * 16 + (ln & 3) * 2 + (reg >> 1) * 8;
            float vx, vy;
            if (which == 0) {           // A[m][k] = x[m][k], k contiguous
                float2 v = *(const float2*)&xb[m * SZ + k];
                vx = v.x; vy = v.y;
            } else {                    // A[m][k] = x[k][m]
                vx = xb[k * SZ + m];
                vy = xb[(k + 1) * SZ + m];
            }
            Af[A_OFF(mt, ks, 0, ln) + reg] = pack_hi(vx, vy);
            Af[A_OFF(mt, ks, 1, ln) + reg] = pack_lo(vx, vy);
        }
        // ---- stage B fragments ----
        // e -> (ks, nt, lane, reg); 2*8*32*2 = 1024 elems, 4 iters
        for (int e = t; e < 1024; e += 256) {
            int reg = e & 1, ln = (e >> 1) & 31, nt = (e >> 6) & 7, ks = e >> 9;
            int n = nt * 8 + (ln >> 2);
            int k = k0 + ks * 16 + (ln & 3) * 2 + reg * 8;
            float2 v = *(const float2*)&wb[(size_t)n * (NC * SZ) + k];
            Bf[B_OFF(ks, 0, nt, ln) + reg] = pack_hi(v.x, v.y);
            Bf[B_OFF(ks, 1, nt, ln) + reg] = pack_lo(v.x, v.y);
        }
        __syncthreads();

        // ---- compute: 2 ks x 5 m x 2 n x 3 terms = 60 HMMA ----
#pragma unroll
        for (int ks = 0; ks < 2; ks++) {
            uint32_t bh[2][2], bl[2][2];
#pragma unroll
            for (int ntl = 0; ntl < 2; ntl++) {
                int nt = ngrp * 2 + ntl;
                *(uint2*)bh[ntl] = *(const uint2*)&Bf[B_OFF(ks, 0, nt, lane)];
                *(uint2*)bl[ntl] = *(const uint2*)&Bf[B_OFF(ks, 1, nt, lane)];
            }
#pragma unroll
            for (int mtl = 0; mtl < 5; mtl++) {
                int mt = mgrp * 5 + mtl;
                uint32_t ah[4], al[4];
                *(uint4*)ah = *(const uint4*)&Af[A_OFF(mt, ks, 0, lane)];
                *(uint4*)al = *(const uint4*)&Af[A_OFF(mt, ks, 1, lane)];
#pragma unroll
                for (int ntl = 0; ntl < 2; ntl++) {
                    hmma(acc[mtl][ntl], ah, bh[ntl]);
                    hmma(acc[mtl][ntl], ah, bl[ntl]);
                    hmma(acc[mtl][ntl], al, bh[ntl]);
                }
            }
        }
        __syncthreads();
    }

    // ---- write partials: pout[o*SZ + m] ----
    float* __restrict__ pout =
        g_part + ((size_t)(which * NCH + cc) * NB + batch) * (NC * SZ);
    const int q = lane & 3, r = lane >> 2;
#pragma unroll
    for (int mtl = 0; mtl < 5; mtl++) {
#pragma unroll
        for (int ntl = 0; ntl < 2; ntl++) {
#pragma unroll
            for (int reg = 0; reg < 4; reg++) {
                int m = mgrp * 80 + mtl * 16 + r + (reg >> 1) * 8;
                int o = (ngrp * 2 + ntl) * 8 + q * 2 + (reg & 1);
                pout[o * SZ + m] = acc[mtl][ntl][reg];
            }
        }
    }
}

// ---------------- Kernel 3: reduce partials, BN-fold, SiLU, s = <b,c> ----------------
__global__ void k_finish(const float* __restrict__ gb, const float* __restrict__ bb,
                         const float* __restrict__ gc, const float* __restrict__ bc) {
    const int o     = blockIdx.x;
    const int batch = blockIdx.y;
    const int t     = threadIdx.x;  // 0..159

    float bsum = 0.f, csum = 0.f;
    const size_t inner = (size_t)o * SZ + t;
    for (int cc = 0; cc < NCH; cc++) {
        bsum += g_part[((size_t)(cc) * NB + batch) * (NC * SZ) + inner];
        csum += g_part[((size_t)(NCH + cc) * NB + batch) * (NC * SZ) + inner];
    }
    float bp = bsum * gb[o] + bb[o];
    float bv = bp / (1.f + expf(-bp));
    float cp = csum * gc[o] + bc[o];
    float cv = cp / (1.f + expf(-cp));

    const size_t idx = (size_t)(batch * NC + o) * SZ + t;
    g_bvec[idx] = bv;
    g_cvec[idx] = cv;

    __shared__ float red[SZ];
    red[t] = bv * cv;
    __syncthreads();
    if (t == 0) {
        float s = 0.f;
        for (int i = 0; i < SZ; i++) s += red[i];
        g_s[batch * NC + o] = s;
    }
}

// ---------------- Kernel 4: rank-1 update + upsample, 4-way Y-split ----------------
__global__ __launch_bounds__(256, 6)
void k_final(float* __restrict__ out) {
    __shared__ float bv[SZ];
    __shared__ float cvE[HW];
    __shared__ float ps[40];

    const int bc = blockIdx.x;
    const int q  = blockIdx.y;
    const int t  = threadIdx.x;
    const float* __restrict__ xsrc = g_x160 + (size_t)bc * SZ * SZ;

    if (t < SZ) bv[t] = g_bvec[(size_t)bc * SZ + t];
    cvE[t] = g_cvec[(size_t)bc * SZ + ((t * 5) >> 3)];
    __syncthreads();

    const float sval = g_s[bc];
    const int warp = t >> 5, lane = t & 31;
    for (int hh = warp; hh < 40; hh += 8) {
        const int h = 40 * q + hh;
        float p = 0.f;
#pragma unroll
        for (int k = 0; k < 5; k++) {
            int w = lane + 32 * k;
            p += xsrc[h * SZ + w] * bv[w];
        }
#pragma unroll
        for (int off = 16; off; off >>= 1) p += __shfl_down_sync(0xffffffffu, p, off);
        if (lane == 0) ps[hh] = p * sval;
    }
    __syncthreads();

    const int r  = t >> 6;
    const int xq = t & 63;
    const int X0 = xq * 4;
    const int wi0 = (X0 * 5) >> 3;
    const int wi1 = ((X0 + 1) * 5) >> 3;
    const int wi2 = ((X0 + 2) * 5) >> 3;
    const int wi3 = ((X0 + 3) * 5) >> 3;
    const float c0 = cvE[X0], c1 = cvE[X0 + 1], c2 = cvE[X0 + 2], c3 = cvE[X0 + 3];

    float* __restrict__ obase = out + (size_t)bc * HW * HW;
    const int Ybeg = 64 * q;
#pragma unroll 2
    for (int Y0 = Ybeg; Y0 < Ybeg + 64; Y0 += 4) {
        const int Y = Y0 + r;
        const int h = (Y * 5) >> 3;
        const float* __restrict__ xr = xsrc + h * SZ;
        const float pv = ps[h - 40 * q];
        float4 v;
        v.x = xr[wi0] + pv * c0;
        v.y = xr[wi1] + pv * c1;
        v.z = xr[wi2] + pv * c2;
        v.w = xr[wi3] + pv * c3;
        *(float4*)&obase[Y * HW + X0] = v;
    }
}

// ---------------- launch ----------------
extern "C" void kernel_launch(void* const* d_in, const int* in_sizes, int n_in,
                              void* d_out, int out_size) {
    const float* x  = (const float*)d_in[0];
    const float* Wb = (const float*)d_in[1];
    const float* Wc = (const float*)d_in[2];
    const float* gb = (const float*)d_in[3];
    const float* bb = (const float*)d_in[4];
    const float* gc = (const float*)d_in[5];
    const float* bc = (const float*)d_in[6];
    float* out = (float*)d_out;

    k_down<<<NB * NC, 256>>>(x);
    k_mma<<<dim3(NCH, NB, 2), 256>>>(Wb, Wc);
    k_finish<<<dim3(NC, NB), 160>>>(gb, bb, gc, bc);
    k_final<<<dim3(NB * NC, 4), 256>>>(out);
}